// round 1
// baseline (speedup 1.0000x reference)
#include <cuda_runtime.h>

// Histogram_Binning: softmax over C=8 -> bin into 15 uniform bins -> LUT gather -> renormalize.
// Layout [B, C, H, W]; channel stride = H*W. One thread processes 4 consecutive W positions
// (float4 per class plane). All transcendental math on the FMA pipe (no MUFU) to stay
// memory-bound.

#define NBINS 15
#define CDIM 8
#define HW_CONST (512 * 512)

// exp(x) for x <= 0, FMA-only. ~1 ulp. Cody-Waite + cephes degree-6 polynomial.
__device__ __forceinline__ float exp_fma(float x) {
    x = fmaxf(x, -87.0f);                              // keep 2^k scale normal
    float k = rintf(x * 1.4426950408889634f);
    float r = fmaf(k, -0.693359375f, x);               // x - k*ln2_hi
    r = fmaf(k, 2.12194440e-4f, r);                    // - k*ln2_lo  (ln2_lo < 0)
    float p = 1.9875691500e-4f;
    p = fmaf(p, r, 1.3981999507e-3f);
    p = fmaf(p, r, 8.3334519073e-3f);
    p = fmaf(p, r, 4.1665795894e-2f);
    p = fmaf(p, r, 1.6666665459e-1f);
    p = fmaf(p, r, 5.0000001201e-1f);
    float z = r * r;
    float e = fmaf(p, z, r) + 1.0f;                    // e^r
    int ik = (int)k;
    float sc = __int_as_float((ik + 127) << 23);       // 2^k
    return e * sc;
}

// 1/s for s in [1, 8], FMA-only (bit-trick seed + Newton). ~0.5-1 ulp after final fused refine.
__device__ __forceinline__ float rcp_fma(float s) {
    float y = __int_as_float(0x7EF311C3 - __float_as_int(s));
    y = y * fmaf(-s, y, 2.0f);
    y = y * fmaf(-s, y, 2.0f);
    y = fmaf(y, fmaf(-s, y, 1.0f), y);
    return y;
}

__global__ void __launch_bounds__(256)
hist_bin_kernel(const float* __restrict__ logits,
                const float* __restrict__ val_freqs,
                float* __restrict__ out,
                int n_quads)  // n_quads = B*H*W/4
{
    __shared__ float s_vf[CDIM * NBINS];
    int t = threadIdx.x;
    if (t < CDIM * NBINS) s_vf[t] = val_freqs[t];
    __syncthreads();

    int idx = blockIdx.x * 256 + t;
    if (idx >= n_quads) return;

    const int hw4 = HW_CONST >> 2;
    int b = idx / hw4;
    int s = (idx - b * hw4) << 2;
    int base = b * (CDIM * HW_CONST) + s;   // < 2^31, int ok

    float4 v[CDIM];
#pragma unroll
    for (int c = 0; c < CDIM; c++)
        v[c] = *reinterpret_cast<const float4*>(logits + base + c * HW_CONST);

    float* vl = reinterpret_cast<float*>(v);  // vl[c*4 + lane]

#pragma unroll
    for (int j = 0; j < 4; j++) {
        // gather the 8 class logits for this spatial position
        float x0 = vl[0 * 4 + j], x1 = vl[1 * 4 + j], x2 = vl[2 * 4 + j], x3 = vl[3 * 4 + j];
        float x4 = vl[4 * 4 + j], x5 = vl[5 * 4 + j], x6 = vl[6 * 4 + j], x7 = vl[7 * 4 + j];

        float m = fmaxf(fmaxf(fmaxf(x0, x1), fmaxf(x2, x3)),
                        fmaxf(fmaxf(x4, x5), fmaxf(x6, x7)));

        float e[CDIM];
        e[0] = exp_fma(x0 - m); e[1] = exp_fma(x1 - m);
        e[2] = exp_fma(x2 - m); e[3] = exp_fma(x3 - m);
        e[4] = exp_fma(x4 - m); e[5] = exp_fma(x5 - m);
        e[6] = exp_fma(x6 - m); e[7] = exp_fma(x7 - m);

        float S = e[0];
#pragma unroll
        for (int c = 1; c < CDIM; c++) S += e[c];

        float rS = rcp_fma(S);

        float cal[CDIM];
        float T = 0.0f;
#pragma unroll
        for (int c = 0; c < CDIM; c++) {
            float q = e[c] * rS;
            q = fmaf(rS, fmaf(-S, q, e[c]), q);   // Markstein refine: q ~= correctly rounded e/S
            float pb = q * (float)NBINS;          // same rounding as reference's probs * 15
            int bin = (int)pb;                    // pb >= 0, trunc == floor
            bin = min(bin, NBINS - 1);
            float cv = s_vf[c * NBINS + bin];
            cal[c] = cv;
            T += cv;
        }

        float rT = rcp_fma(T);
#pragma unroll
        for (int c = 0; c < CDIM; c++)
            vl[c * 4 + j] = cal[c] * rT;
    }

#pragma unroll
    for (int c = 0; c < CDIM; c++)
        *reinterpret_cast<float4*>(out + base + c * HW_CONST) = v[c];
}

extern "C" void kernel_launch(void* const* d_in, const int* in_sizes, int n_in,
                              void* d_out, int out_size) {
    const float* logits    = (const float*)d_in[0];
    const float* val_freqs = (const float*)d_in[1];
    float* out = (float*)d_out;

    int total   = in_sizes[0];            // B*C*H*W = 33,554,432
    int n_quads = total / (CDIM * 4);     // 1,048,576
    int threads = 256;
    int blocks  = (n_quads + threads - 1) / threads;
    hist_bin_kernel<<<blocks, threads>>>(logits, val_freqs, out, n_quads);
}